// round 5
// baseline (speedup 1.0000x reference)
#include <cuda_runtime.h>

#define NN 4096
#define MM 128
#define KK 32
#define GG 16
#define NS 8
#define CHUNK (NN / NS)   // 512

// Scratch (device globals: no runtime allocation allowed)
__device__ float  g_V[NN * KK];                // transported-solve vectors v_i
__device__ float4 g_OP4[MM * 256];             // pre-reduced omega_parent mean
__device__ float  g_partZ[MM * NS];
__device__ float  g_partCnt[MM * NS];
__device__ float  g_partS1[MM * NS * KK];
__device__ float  g_partS2[MM * NS * KK * KK];
__device__ float  g_psiPart[MM * 4];

// ---------------------------------------------------------------------------
// Kernel 1 (fused): per-i reduce omega_child over G + solve A x = b -> v_i.
// Two systems per block (256 threads). High-MLP load phase: all 16 g-loads
// batched in registers (launch_bounds(256,2) -> 128-reg budget, MLP=16).
// ---------------------------------------------------------------------------
__global__ void __launch_bounds__(256, 2)
solve_kernel(const float* __restrict__ omega_child,
             const float* __restrict__ mu_s)
{
    __shared__ float A[2][KK * 33];
    const int sub = threadIdx.x >> 7;      // which system
    const int tt  = threadIdx.x & 127;
    const int i = blockIdx.x * 2 + sub;
    const int lane = tt & 31, w = tt >> 5;
    float* Am = A[sub];

    const float4* oc4 = (const float4*)(omega_child + (size_t)i * GG * KK * KK);

    // Load + reduce omega_child[i] over G: 2 q's per thread, 16 batched
    // LDG.128 per q -> deep MLP.
    #pragma unroll
    for (int h = 0; h < 2; h++) {
        const int q = tt + h * 128;
        float4 v[GG];
        #pragma unroll
        for (int g = 0; g < GG; g++) v[g] = oc4[g * 256 + q];
        #pragma unroll
        for (int st = GG / 2; st >= 1; st >>= 1) {
            #pragma unroll
            for (int j = 0; j < st; j++) {
                v[j].x += v[j + st].x; v[j].y += v[j + st].y;
                v[j].z += v[j + st].z; v[j].w += v[j + st].w;
            }
        }
        const int e = q * 4;
        const int r = e >> 5, c = e & 31;
        Am[r * 33 + c + 0] = v[0].x;
        Am[r * 33 + c + 1] = v[0].y;
        Am[r * 33 + c + 2] = v[0].z;
        Am[r * 33 + c + 3] = v[0].w;
    }
    if (tt < KK) {
        const float* mu = mu_s + (size_t)i * GG * KK;
        float s = 0.f;
        #pragma unroll
        for (int g = 0; g < GG; g++) s += mu[g * KK + tt];
        Am[tt * 33 + 32] = s;
    }
    __syncthreads();

    // Forward elimination (SPD: no pivoting). Column k is read but never
    // written (left stale) -> no intra-warp RAW hazard on Am[r][k].
    for (int k = 0; k < KK - 1; k++) {
        const float invp = 1.0f / Am[k * 33 + k];
        const int c = k + 1 + lane;
        for (int r = k + 1 + w; r < KK; r += 4) {
            const float m = Am[r * 33 + k] * invp;
            if (c <= 32) Am[r * 33 + c] -= m * Am[k * 33 + c];
        }
        __syncthreads();
    }

    // Backward Jordan on the b column only.
    for (int k = KK - 1; k >= 1; k--) {
        if (tt < k) {
            const float xk = Am[k * 33 + 32] / Am[k * 33 + k];
            Am[tt * 33 + 32] -= Am[tt * 33 + k] * xk;
        }
        __syncthreads();
    }
    if (tt < KK)
        g_V[(size_t)i * KK + tt] = Am[tt * 33 + 32] / Am[tt * 33 + tt];
}

// ---------------------------------------------------------------------------
// Kernel 1b: streaming mean of omega_parent over G -> g_OP4 (512 KB).
// ---------------------------------------------------------------------------
__global__ void reduce_op_kernel(const float4* __restrict__ op4)
{
    const int gid = blockIdx.x * blockDim.x + threadIdx.x;  // 0..32767
    const int a = gid >> 8;
    const int q = gid & 255;
    const float4* p = op4 + (size_t)a * (GG * 256) + q;
    float4 v[GG];
    #pragma unroll
    for (int g = 0; g < GG; g++) v[g] = p[g * 256];
    #pragma unroll
    for (int st = GG / 2; st >= 1; st >>= 1) {
        #pragma unroll
        for (int j = 0; j < st; j++) {
            v[j].x += v[j + st].x; v[j].y += v[j + st].y;
            v[j].z += v[j + st].z; v[j].w += v[j + st].w;
        }
    }
    const float inv = 1.0f / 16.0f;
    v[0].x *= inv; v[0].y *= inv; v[0].z *= inv; v[0].w *= inv;
    g_OP4[gid] = v[0];
}

// ---------------------------------------------------------------------------
// Kernel 2: per (cluster a, i-split s): accumulate
//   Z = sum w, cnt = sum mask, S1[l] = sum w v_l, S2[l,m] = sum w v_l v_m
// Rows carry the weight: staged as duplicated pairs (w v_l, w v_l) so the
// inner loop needs NO pack-MOVs. Cols staged as plain v (float4 vectors).
// Double-buffered, one __syncthreads per tile; next tile's g_V load is
// issued before the FMA loop (latency hidden under 192 issues of compute).
// Inner iter: 2x ld.shared.v2.b64 + 4x fma.rn.f32x2 = 6 issues / 256 MACs.
// ---------------------------------------------------------------------------
__global__ void __launch_bounds__(128, 6)
accum_kernel(const float* __restrict__ W)
{
    const int a = blockIdx.x;
    const int s = blockIdx.y;
    const int t = threadIdx.x;     // 0..127
    const int i0base = s * CHUNK;

    __shared__ float sw[CHUNK];            // masked mean weights (2 KB)
    __shared__ float sc_[2][32 * 36];      // v cols, row stride 36
    __shared__ float sd_[2][32 * 68];      // dup (w*v) pairs, row stride 68
    __shared__ float zred[4], cred[4];

    // ---- Phase 0: preload + reduce all W for this chunk (4 i's per thread)
    float accZ = 0.f, accCnt = 0.f;
    #pragma unroll
    for (int r = 0; r < 4; r++) {
        const int il = t + r * 128;
        const float4* wp =
            (const float4*)(W + ((size_t)(i0base + il) * MM + a) * GG);
        const float4 w0 = wp[0], w1 = wp[1], w2 = wp[2], w3 = wp[3];
        const float sum = (w0.x + w0.y + w0.z + w0.w)
                        + (w1.x + w1.y + w1.z + w1.w)
                        + (w2.x + w2.y + w2.z + w2.w)
                        + (w3.x + w3.y + w3.z + w3.w);
        const float wm = sum * 0.0625f;
        const int ok = (wm >= 1e-6f);
        sw[il] = ok ? wm : 0.0f;
        accZ += ok ? wm : 0.0f;
        accCnt += ok ? 1.0f : 0.0f;
    }
    #pragma unroll
    for (int off = 16; off; off >>= 1) {
        accZ   += __shfl_xor_sync(0xffffffffu, accZ, off);
        accCnt += __shfl_xor_sync(0xffffffffu, accCnt, off);
    }
    if ((t & 31) == 0) { zred[t >> 5] = accZ; cred[t >> 5] = accCnt; }
    __syncthreads();
    if (t == 0) {
        g_partZ[a * NS + s]   = zred[0] + zred[1] + zred[2] + zred[3];
        g_partCnt[a * NS + s] = cred[0] + cred[1] + cred[2] + cred[3];
    }

    const int rp = t >> 3;      // 0..15 (row pair: rows 2rp, 2rp+1)
    const int cq = t & 7;       // 0..7  (col quad: cols 4cq..4cq+3)
    const int ii_s = t >> 2;    // staging row 0..31
    const int cc_s = t & 3;     // staging quad 0..3

    unsigned long long acc00 = 0ull, acc01 = 0ull;
    unsigned long long acc10 = 0ull, acc11 = 0ull;
    float4 s1a = make_float4(0.f, 0.f, 0.f, 0.f);
    float4 s1b = make_float4(0.f, 0.f, 0.f, 0.f);

    const unsigned sdb0 = (unsigned)__cvta_generic_to_shared(sd_[0]);
    const unsigned sdb1 = (unsigned)__cvta_generic_to_shared(sd_[1]);
    const unsigned scb0 = (unsigned)__cvta_generic_to_shared(sc_[0]);
    const unsigned scb1 = (unsigned)__cvta_generic_to_shared(sc_[1]);

    // staging helper (macro-free inline lambda)
    auto stage = [&](int b, float4 v0, float4 v1, float wc) {
        float* sc = sc_[b];
        float* sd = sd_[b];
        float4 d0, d1;
        d0.x = wc * v0.x; d0.y = wc * v0.y; d0.z = wc * v0.z; d0.w = wc * v0.w;
        d1.x = wc * v1.x; d1.y = wc * v1.y; d1.z = wc * v1.z; d1.w = wc * v1.w;
        s1a.x += d0.x; s1a.y += d0.y; s1a.z += d0.z; s1a.w += d0.w;
        s1b.x += d1.x; s1b.y += d1.y; s1b.z += d1.z; s1b.w += d1.w;
        *(float4*)(sc + ii_s * 36 + cc_s * 4)      = v0;  // cols 4cc..4cc+3
        *(float4*)(sc + ii_s * 36 + 16 + cc_s * 4) = v1;  // cols 16+4cc..
        float2* pd = (float2*)(sd + ii_s * 68);
        pd[4 * cc_s + 0]      = make_float2(d0.x, d0.x);
        pd[4 * cc_s + 1]      = make_float2(d0.y, d0.y);
        pd[4 * cc_s + 2]      = make_float2(d0.z, d0.z);
        pd[4 * cc_s + 3]      = make_float2(d0.w, d0.w);
        pd[16 + 4 * cc_s + 0] = make_float2(d1.x, d1.x);
        pd[16 + 4 * cc_s + 1] = make_float2(d1.y, d1.y);
        pd[16 + 4 * cc_s + 2] = make_float2(d1.z, d1.z);
        pd[16 + 4 * cc_s + 3] = make_float2(d1.w, d1.w);
    };

    // ---- prologue: tile 0
    {
        const float4* vp = (const float4*)g_V + (size_t)(i0base + ii_s) * 8;
        stage(0, vp[cc_s], vp[cc_s + 4], sw[ii_s]);
    }
    __syncthreads();

    for (int tile = 0; tile < CHUNK / 32; tile++) {
        const int buf = tile & 1;
        float4 n0, n1; float wn = 0.f;
        if (tile < CHUNK / 32 - 1) {
            const int iloc = (tile + 1) * 32 + ii_s;
            const float4* vp = (const float4*)g_V + (size_t)(i0base + iloc) * 8;
            n0 = vp[cc_s]; n1 = vp[cc_s + 4]; wn = sw[iloc];
        }

        const unsigned ad = (buf ? sdb1 : sdb0) + rp * 16;
        const unsigned ac = (buf ? scb1 : scb0) + cq * 16;
        #pragma unroll
        for (int ii = 0; ii < 32; ii++) {
            unsigned long long xl0p, xl1p, xm01, xm23;
            asm volatile("ld.shared.v2.b64 {%0,%1}, [%2];"
                         : "=l"(xl0p), "=l"(xl1p) : "r"(ad + ii * 272));
            asm volatile("ld.shared.v2.b64 {%0,%1}, [%2];"
                         : "=l"(xm01), "=l"(xm23) : "r"(ac + ii * 144));
            asm("fma.rn.f32x2 %0, %1, %2, %0;" : "+l"(acc00) : "l"(xl0p), "l"(xm01));
            asm("fma.rn.f32x2 %0, %1, %2, %0;" : "+l"(acc01) : "l"(xl0p), "l"(xm23));
            asm("fma.rn.f32x2 %0, %1, %2, %0;" : "+l"(acc10) : "l"(xl1p), "l"(xm01));
            asm("fma.rn.f32x2 %0, %1, %2, %0;" : "+l"(acc11) : "l"(xl1p), "l"(xm23));
        }

        if (tile < CHUNK / 32 - 1) stage(buf ^ 1, n0, n1, wn);
        __syncthreads();
    }

    // ---- S2 partial: thread owns 8 unique (l,m) slots (2 rows x 4 cols)
    {
        float b00, b01, b02, b03, b10, b11, b12, b13;
        asm("mov.b64 {%0,%1}, %2;" : "=f"(b00), "=f"(b01) : "l"(acc00));
        asm("mov.b64 {%0,%1}, %2;" : "=f"(b02), "=f"(b03) : "l"(acc01));
        asm("mov.b64 {%0,%1}, %2;" : "=f"(b10), "=f"(b11) : "l"(acc10));
        asm("mov.b64 {%0,%1}, %2;" : "=f"(b12), "=f"(b13) : "l"(acc11));
        float* p2 = g_partS2 + ((size_t)a * NS + s) * (KK * KK)
                  + (2 * rp) * KK + 4 * cq;
        *(float4*)p2        = make_float4(b00, b01, b02, b03);
        *(float4*)(p2 + KK) = make_float4(b10, b11, b12, b13);
    }

    // ---- S1: dump per-thread partials into sc_[0] (free now), reduce over ii
    *(float4*)(sc_[0] + ii_s * 36 + cc_s * 4)      = s1a;
    *(float4*)(sc_[0] + ii_s * 36 + 16 + cc_s * 4) = s1b;
    __syncthreads();
    if (t < 32) {
        float ssum = 0.f;
        #pragma unroll
        for (int ii = 0; ii < 32; ii++) ssum += sc_[0][ii * 36 + t];
        g_partS1[((size_t)a * NS + s) * KK + t] = ssum;
    }
}

// ---------------------------------------------------------------------------
// Kernel 3a: psi partials. grid (128 clusters x 4 slices), 256 threads.
//   S = op_avg^T op_avg,  C = S2/Zs - vbar vbar^T,  psi = sum S.*C
// ---------------------------------------------------------------------------
__global__ void finalize_part_kernel(void)
{
    const int a = blockIdx.x;
    const int y = blockIdx.y;
    const int t = threadIdx.x;    // 0..255
    __shared__ float op[32 * 33];
    __shared__ float vbar[32];
    __shared__ float zs;
    __shared__ float red[8];

    {
        const float4 s = g_OP4[a * 256 + t];
        const int e = t * 4;
        const int r = e >> 5, c = e & 31;
        op[r * 33 + c + 0] = s.x;
        op[r * 33 + c + 1] = s.y;
        op[r * 33 + c + 2] = s.z;
        op[r * 33 + c + 3] = s.w;
    }
    if (t == 0) {
        float Z = 0.f;
        #pragma unroll
        for (int ss = 0; ss < NS; ss++) Z += g_partZ[a * NS + ss];
        zs = (Z > 0.f) ? Z : 1.0f;
    }
    if (t < KK) {
        float s1 = 0.f;
        #pragma unroll
        for (int ss = 0; ss < NS; ss++)
            s1 += g_partS1[(a * NS + ss) * KK + t];
        vbar[t] = s1;
    }
    __syncthreads();
    const float Zs = zs;
    if (t < KK) vbar[t] = vbar[t] / Zs;
    __syncthreads();

    const int e = y * 256 + t;
    const int l = e >> 5, m = e & 31;
    float s2 = 0.f;
    #pragma unroll
    for (int ss = 0; ss < NS; ss++)
        s2 += g_partS2[((size_t)a * NS + ss) * (KK * KK) + e];
    const float C = s2 / Zs - vbar[l] * vbar[m];
    float S = 0.f;
    #pragma unroll
    for (int k = 0; k < KK; k++)
        S += op[k * 33 + l] * op[k * 33 + m];
    float psi = S * C;

    #pragma unroll
    for (int off = 16; off; off >>= 1)
        psi += __shfl_xor_sync(0xffffffffu, psi, off);
    if ((t & 31) == 0) red[t >> 5] = psi;
    __syncthreads();
    if (t == 0) {
        float tot = 0.f;
        #pragma unroll
        for (int ww = 0; ww < 8; ww++) tot += red[ww];
        g_psiPart[a * 4 + y] = tot;
    }
}

// ---------------------------------------------------------------------------
// Kernel 3b: combine. One block of 128 threads; thread a -> out[a].
// ---------------------------------------------------------------------------
__global__ void finalize_combine_kernel(float* __restrict__ out)
{
    const int a = threadIdx.x;
    float cnt = 0.f;
    #pragma unroll
    for (int ss = 0; ss < NS; ss++) cnt += g_partCnt[a * NS + ss];
    const float p = g_psiPart[a * 4 + 0] + g_psiPart[a * 4 + 1]
                  + g_psiPart[a * 4 + 2] + g_psiPart[a * 4 + 3];
    out[a] = (cnt >= 2.0f) ? p : 0.0f;
}

// ---------------------------------------------------------------------------
extern "C" void kernel_launch(void* const* d_in, const int* in_sizes, int n_in,
                              void* d_out, int out_size)
{
    const float* W  = (const float*)d_in[0];   // (N, M, G)
    const float* mu = (const float*)d_in[1];   // (N, G, K)
    const float* oc = (const float*)d_in[2];   // (N, G, K, K)
    const float* op = (const float*)d_in[3];   // (M, G, K, K)
    float* out = (float*)d_out;                // (M,)

    solve_kernel<<<NN / 2, 256>>>(oc, mu);
    reduce_op_kernel<<<MM, 256>>>((const float4*)op);
    accum_kernel<<<dim3(MM, NS), 128>>>(W);
    finalize_part_kernel<<<dim3(MM, 4), 256>>>();
    finalize_combine_kernel<<<1, MM>>>(out);
}

// round 6
// speedup vs baseline: 1.2670x; 1.2670x over previous
#include <cuda_runtime.h>

#define NN 4096
#define MM 128
#define KK 32
#define GG 16
#define NS 8
#define CHUNK (NN / NS)   // 512

// Scratch (device globals: no runtime allocation allowed)
__device__ float  g_V[NN * KK];                // transported-solve vectors v_i
__device__ float4 g_OP4[MM * 256];             // pre-reduced omega_parent mean
__device__ float  g_partZ[MM * NS];
__device__ float  g_partCnt[MM * NS];
__device__ float  g_partS1[MM * NS * KK];
__device__ float  g_partS2[MM * NS * KK * KK];
__device__ float  g_psiPart[MM * 4];

// ---------------------------------------------------------------------------
// Kernel 1: warp-per-system fused reduce+solve. 256 thr = 8 warps = 8 systems
// per block; NO block barriers (only __syncwarp), so the streaming load phase
// of some warps always overlaps the elimination of others.
// Each warp: reduce omega_child[i] over G (coalesced, 8 float4 accumulators
// -> deep MLP), stage A into its private smem slab (row stride 36, b at col
// 32), Gaussian elimination (SPD, no pivoting) + back-substitution.
// ---------------------------------------------------------------------------
__global__ void __launch_bounds__(256)
solve_kernel(const float* __restrict__ omega_child,
             const float* __restrict__ mu_s)
{
    __shared__ float A[8][32 * 36];
    const int w = threadIdx.x >> 5, lane = threadIdx.x & 31;
    const int i = blockIdx.x * 8 + w;
    float* Am = A[w];

    const float4* oc4 = (const float4*)(omega_child + (size_t)i * GG * KK * KK);

    // ---- Phase 1: G-reduction. lane handles q = lane + 32j, j=0..7.
    float4 acc[8];
    #pragma unroll
    for (int j = 0; j < 8; j++) acc[j] = oc4[lane + 32 * j];
    #pragma unroll
    for (int g = 1; g < GG; g++) {
        #pragma unroll
        for (int j = 0; j < 8; j++) {
            const float4 v = oc4[g * 256 + lane + 32 * j];
            acc[j].x += v.x; acc[j].y += v.y;
            acc[j].z += v.z; acc[j].w += v.w;
        }
    }
    // store: q -> row = q>>3, col = 4*(q&7)  (byte-offset 16B aligned)
    #pragma unroll
    for (int j = 0; j < 8; j++) {
        const int q = lane + 32 * j;
        *(float4*)(Am + (q >> 3) * 36 + (q & 7) * 4) = acc[j];
    }
    // b_r = sum_g mu[i,g,r]
    {
        const float* mu = mu_s + (size_t)i * GG * KK;
        float b = 0.f;
        #pragma unroll
        for (int g = 0; g < GG; g++) b += mu[g * KK + lane];
        Am[lane * 36 + 32] = b;
    }
    __syncwarp();

    // ---- Phase 2: forward elimination (warp-private; __syncwarp per k)
    for (int k = 0; k < KK - 1; k++) {
        const float pinv = 1.0f / Am[k * 36 + k];          // broadcast
        const float akc  = Am[k * 36 + lane];              // row k, col lane
        const float akb  = Am[k * 36 + 32];
        for (int r = k + 1; r < KK; r++) {
            const float m = Am[r * 36 + k] * pinv;         // broadcast
            if (lane > k)  Am[r * 36 + lane] -= m * akc;
            if (lane == k) Am[r * 36 + 32]   -= m * akb;
        }
        __syncwarp();
    }

    // ---- Phase 3: back-substitution (x written into col 32 in place)
    for (int k = KK - 1; k >= 1; k--) {
        const float xk = Am[k * 36 + 32] / Am[k * 36 + k]; // broadcast
        if (lane == k)     Am[k * 36 + 32] = xk;
        else if (lane < k) Am[lane * 36 + 32] -= Am[lane * 36 + k] * xk;
        __syncwarp();
    }
    float xr = Am[lane * 36 + 32];
    if (lane == 0) xr /= Am[0];
    g_V[(size_t)i * KK + lane] = xr;
}

// ---------------------------------------------------------------------------
// Kernel 1b: streaming mean of omega_parent over G -> g_OP4 (512 KB).
// ---------------------------------------------------------------------------
__global__ void reduce_op_kernel(const float4* __restrict__ op4)
{
    const int gid = blockIdx.x * blockDim.x + threadIdx.x;  // 0..32767
    const int a = gid >> 8;
    const int q = gid & 255;
    const float4* p = op4 + (size_t)a * (GG * 256) + q;
    float4 s0 = p[0];
    float4 s1 = p[256];
    #pragma unroll
    for (int g = 2; g < GG; g += 2) {
        const float4 va = p[g * 256];
        const float4 vb = p[(g + 1) * 256];
        s0.x += va.x; s0.y += va.y; s0.z += va.z; s0.w += va.w;
        s1.x += vb.x; s1.y += vb.y; s1.z += vb.z; s1.w += vb.w;
    }
    const float inv = 1.0f / 16.0f;
    s0.x = (s0.x + s1.x) * inv; s0.y = (s0.y + s1.y) * inv;
    s0.z = (s0.z + s1.z) * inv; s0.w = (s0.w + s1.w) * inv;
    g_OP4[gid] = s0;
}

// ---------------------------------------------------------------------------
// Kernel 2: per (cluster a, i-split s): S2 = sum_i w v v^T via x = sqrt(w) v,
// S2 = sum x x^T; plus Z, cnt, S1 = sum w v.
// 8x8 register tile per thread, ii-dim split 8 ways:
//   t = ig*16 + tl;  ig = t>>4 handles ii = 4*ig..4*ig+3 per 32-tile;
//   tl: rt = tl>>2 -> rows rt*8..+7, ct = tl&3 -> cols ct*8..+7.
// Per ii: 4x LDS.128 from ONE array (rows+cols) + 8 packs + 32 fma.f32x2
//   = 64 MACs/lane at 1 B/MAC of crossbar traffic (vs 3 in the 2x4 version).
// Cross-thread ig-partials reduced through smem in 8 rounds at the end.
// ---------------------------------------------------------------------------
__global__ void __launch_bounds__(128, 4)
accum_kernel(const float* __restrict__ W)
{
    const int a = blockIdx.x;
    const int s = blockIdx.y;
    const int t = threadIdx.x;     // 0..127
    const int i0base = s * CHUNK;

    __shared__ float sw[CHUNK];          // sqrt of masked mean weights (2 KB)
    __shared__ float sx[32 * 36];        // sqrt(w)*v tile, row stride 36
    __shared__ float zred[4], cred[4];

    // ---- Phase 0: preload + reduce all W for this chunk (4 i's per thread)
    float accZ = 0.f, accCnt = 0.f;
    #pragma unroll
    for (int r = 0; r < 4; r++) {
        const int il = t + r * 128;
        const float4* wp =
            (const float4*)(W + ((size_t)(i0base + il) * MM + a) * GG);
        const float4 w0 = wp[0], w1 = wp[1], w2 = wp[2], w3 = wp[3];
        const float sum = (w0.x + w0.y + w0.z + w0.w)
                        + (w1.x + w1.y + w1.z + w1.w)
                        + (w2.x + w2.y + w2.z + w2.w)
                        + (w3.x + w3.y + w3.z + w3.w);
        const float wm = sum * 0.0625f;
        const int ok = (wm >= 1e-6f);
        const float wmm = ok ? wm : 0.0f;
        sw[il] = sqrtf(wmm);
        accZ += wmm;
        accCnt += ok ? 1.0f : 0.0f;
    }
    #pragma unroll
    for (int off = 16; off; off >>= 1) {
        accZ   += __shfl_xor_sync(0xffffffffu, accZ, off);
        accCnt += __shfl_xor_sync(0xffffffffu, accCnt, off);
    }
    if ((t & 31) == 0) { zred[t >> 5] = accZ; cred[t >> 5] = accCnt; }
    __syncthreads();
    if (t == 0) {
        g_partZ[a * NS + s]   = zred[0] + zred[1] + zred[2] + zred[3];
        g_partCnt[a * NS + s] = cred[0] + cred[1] + cred[2] + cred[3];
    }

    const int ig = t >> 4;      // ii-group 0..7
    const int tl = t & 15;
    const int rt = tl >> 2;     // row-oct
    const int ct = tl & 3;      // col-oct
    const int ii_s = t >> 2;    // staging row 0..31
    const int cc_s = t & 3;     // staging quad 0..3

    unsigned long long acc[8][4];
    #pragma unroll
    for (int rr = 0; rr < 8; rr++)
        #pragma unroll
        for (int p = 0; p < 4; p++) acc[rr][p] = 0ull;

    float4 s1a = make_float4(0.f, 0.f, 0.f, 0.f);
    float4 s1b = make_float4(0.f, 0.f, 0.f, 0.f);

    const unsigned sxb = (unsigned)__cvta_generic_to_shared(sx);
    const unsigned rbase = sxb + ig * 4 * 144 + rt * 32;   // row-oct addr
    const unsigned cbase = sxb + ig * 4 * 144 + ct * 32;   // col-oct addr

    // prefetch tile 0
    float4 n0, n1; float wn;
    {
        const float4* vp = (const float4*)g_V + (size_t)(i0base + ii_s) * 8;
        n0 = vp[cc_s]; n1 = vp[cc_s + 4]; wn = sw[ii_s];
    }

    for (int tile = 0; tile < CHUNK / 32; tile++) {
        // ---- stage x = sqrt(w) * v ; accumulate S1 contribution w*v
        {
            float4 x0, x1;
            x0.x = wn * n0.x; x0.y = wn * n0.y; x0.z = wn * n0.z; x0.w = wn * n0.w;
            x1.x = wn * n1.x; x1.y = wn * n1.y; x1.z = wn * n1.z; x1.w = wn * n1.w;
            s1a.x += wn * x0.x; s1a.y += wn * x0.y;
            s1a.z += wn * x0.z; s1a.w += wn * x0.w;
            s1b.x += wn * x1.x; s1b.y += wn * x1.y;
            s1b.z += wn * x1.z; s1b.w += wn * x1.w;
            *(float4*)(sx + ii_s * 36 + cc_s * 4)      = x0;
            *(float4*)(sx + ii_s * 36 + 16 + cc_s * 4) = x1;
        }
        __syncthreads();

        // prefetch next tile (L2 latency hides under the FMA loop)
        if (tile < CHUNK / 32 - 1) {
            const int iloc = (tile + 1) * 32 + ii_s;
            const float4* vp = (const float4*)g_V + (size_t)(i0base + iloc) * 8;
            n0 = vp[cc_s]; n1 = vp[cc_s + 4]; wn = sw[iloc];
        }

        // ---- 8x8 outer-product accumulation over this thread's 4 ii's
        #pragma unroll
        for (int k = 0; k < 4; k++) {
            const unsigned ro = rbase + k * 144;
            const unsigned co = cbase + k * 144;
            float r0, r1, r2, r3, r4_, r5, r6, r7;
            asm volatile("ld.shared.v4.f32 {%0,%1,%2,%3}, [%4];"
                         : "=f"(r0), "=f"(r1), "=f"(r2), "=f"(r3) : "r"(ro));
            asm volatile("ld.shared.v4.f32 {%0,%1,%2,%3}, [%4];"
                         : "=f"(r4_), "=f"(r5), "=f"(r6), "=f"(r7)
                         : "r"(ro + 16));
            unsigned long long c01, c23, c45, c67;
            asm volatile("ld.shared.v2.b64 {%0,%1}, [%2];"
                         : "=l"(c01), "=l"(c23) : "r"(co));
            asm volatile("ld.shared.v2.b64 {%0,%1}, [%2];"
                         : "=l"(c45), "=l"(c67) : "r"(co + 16));
            const float rv[8] = {r0, r1, r2, r3, r4_, r5, r6, r7};
            #pragma unroll
            for (int rr = 0; rr < 8; rr++) {
                unsigned long long d;
                asm("mov.b64 %0, {%1,%1};" : "=l"(d) : "f"(rv[rr]));
                asm("fma.rn.f32x2 %0, %1, %2, %0;" : "+l"(acc[rr][0]) : "l"(d), "l"(c01));
                asm("fma.rn.f32x2 %0, %1, %2, %0;" : "+l"(acc[rr][1]) : "l"(d), "l"(c23));
                asm("fma.rn.f32x2 %0, %1, %2, %0;" : "+l"(acc[rr][2]) : "l"(d), "l"(c45));
                asm("fma.rn.f32x2 %0, %1, %2, %0;" : "+l"(acc[rr][3]) : "l"(d), "l"(c67));
            }
        }
        __syncthreads();
    }

    // ---- S1: dump per-thread partials into sx (free now), reduce over ii
    *(float4*)(sx + ii_s * 36 + cc_s * 4)      = s1a;
    *(float4*)(sx + ii_s * 36 + 16 + cc_s * 4) = s1b;
    __syncthreads();
    if (t < 32) {
        float ssum = 0.f;
        #pragma unroll
        for (int ii = 0; ii < 32; ii++) ssum += sx[ii * 36 + t];
        g_partS1[((size_t)a * NS + s) * KK + t] = ssum;
    }

    // ---- S2: reduce 8 ig-partials per output through smem, 8 rounds.
    // Round rg: thread writes its row rg (8 floats) at sx[ig*132 + tl*8];
    // reader u sums sx[ig*132 + u] over ig, writes (R,C) =
    // ((u>>5)*8 + rg, ((u>>3)&3)*8 + (u&7)).
    float* p2base = g_partS2 + ((size_t)a * NS + s) * (KK * KK);
    #pragma unroll
    for (int rg = 0; rg < 8; rg++) {
        __syncthreads();
        float p0, p1, p2, p3, p4, p5, p6, p7;
        asm("mov.b64 {%0,%1}, %2;" : "=f"(p0), "=f"(p1) : "l"(acc[rg][0]));
        asm("mov.b64 {%0,%1}, %2;" : "=f"(p2), "=f"(p3) : "l"(acc[rg][1]));
        asm("mov.b64 {%0,%1}, %2;" : "=f"(p4), "=f"(p5) : "l"(acc[rg][2]));
        asm("mov.b64 {%0,%1}, %2;" : "=f"(p6), "=f"(p7) : "l"(acc[rg][3]));
        float* dst = sx + ig * 132 + tl * 8;
        *(float4*)dst       = make_float4(p0, p1, p2, p3);
        *(float4*)(dst + 4) = make_float4(p4, p5, p6, p7);
        __syncthreads();
        float ssum = 0.f;
        #pragma unroll
        for (int g = 0; g < 8; g++) ssum += sx[g * 132 + t];
        const int R = (t >> 5) * 8 + rg;
        const int C = ((t >> 3) & 3) * 8 + (t & 7);
        p2base[R * KK + C] = ssum;
    }
}

// ---------------------------------------------------------------------------
// Kernel 3a: psi partials. grid (128 clusters x 4 slices), 256 threads.
//   S = op_avg^T op_avg,  C = S2/Zs - vbar vbar^T,  psi = sum S.*C
// ---------------------------------------------------------------------------
__global__ void finalize_part_kernel(void)
{
    const int a = blockIdx.x;
    const int y = blockIdx.y;
    const int t = threadIdx.x;    // 0..255
    __shared__ float op[32 * 33];
    __shared__ float vbar[32];
    __shared__ float zs;
    __shared__ float red[8];

    {
        const float4 s = g_OP4[a * 256 + t];
        const int e = t * 4;
        const int r = e >> 5, c = e & 31;
        op[r * 33 + c + 0] = s.x;
        op[r * 33 + c + 1] = s.y;
        op[r * 33 + c + 2] = s.z;
        op[r * 33 + c + 3] = s.w;
    }
    if (t == 0) {
        float Z = 0.f;
        #pragma unroll
        for (int ss = 0; ss < NS; ss++) Z += g_partZ[a * NS + ss];
        zs = (Z > 0.f) ? Z : 1.0f;
    }
    if (t < KK) {
        float s1 = 0.f;
        #pragma unroll
        for (int ss = 0; ss < NS; ss++)
            s1 += g_partS1[(a * NS + ss) * KK + t];
        vbar[t] = s1;
    }
    __syncthreads();
    const float Zs = zs;
    if (t < KK) vbar[t] = vbar[t] / Zs;
    __syncthreads();

    const int e = y * 256 + t;
    const int l = e >> 5, m = e & 31;
    float s2 = 0.f;
    #pragma unroll
    for (int ss = 0; ss < NS; ss++)
        s2 += g_partS2[((size_t)a * NS + ss) * (KK * KK) + e];
    const float C = s2 / Zs - vbar[l] * vbar[m];
    float S = 0.f;
    #pragma unroll
    for (int k = 0; k < KK; k++)
        S += op[k * 33 + l] * op[k * 33 + m];
    float psi = S * C;

    #pragma unroll
    for (int off = 16; off; off >>= 1)
        psi += __shfl_xor_sync(0xffffffffu, psi, off);
    if ((t & 31) == 0) red[t >> 5] = psi;
    __syncthreads();
    if (t == 0) {
        float tot = 0.f;
        #pragma unroll
        for (int ww = 0; ww < 8; ww++) tot += red[ww];
        g_psiPart[a * 4 + y] = tot;
    }
}

// ---------------------------------------------------------------------------
// Kernel 3b: combine. One block of 128 threads; thread a -> out[a].
// ---------------------------------------------------------------------------
__global__ void finalize_combine_kernel(float* __restrict__ out)
{
    const int a = threadIdx.x;
    float cnt = 0.f;
    #pragma unroll
    for (int ss = 0; ss < NS; ss++) cnt += g_partCnt[a * NS + ss];
    const float p = g_psiPart[a * 4 + 0] + g_psiPart[a * 4 + 1]
                  + g_psiPart[a * 4 + 2] + g_psiPart[a * 4 + 3];
    out[a] = (cnt >= 2.0f) ? p : 0.0f;
}

// ---------------------------------------------------------------------------
extern "C" void kernel_launch(void* const* d_in, const int* in_sizes, int n_in,
                              void* d_out, int out_size)
{
    const float* W  = (const float*)d_in[0];   // (N, M, G)
    const float* mu = (const float*)d_in[1];   // (N, G, K)
    const float* oc = (const float*)d_in[2];   // (N, G, K, K)
    const float* op = (const float*)d_in[3];   // (M, G, K, K)
    float* out = (float*)d_out;                // (M,)

    solve_kernel<<<NN / 8, 256>>>(oc, mu);
    reduce_op_kernel<<<MM, 256>>>((const float4*)op);
    accum_kernel<<<dim3(MM, NS), 128>>>(W);
    finalize_part_kernel<<<dim3(MM, 4), 256>>>();
    finalize_combine_kernel<<<1, MM>>>(out);
}

// round 7
// speedup vs baseline: 1.2990x; 1.0253x over previous
#include <cuda_runtime.h>

#define NN 4096
#define MM 128
#define KK 32
#define GG 16
#define NS 8
#define CHUNK (NN / NS)   // 512

// Scratch (device globals: no runtime allocation allowed)
__device__ float  g_V[NN * KK];                // transported-solve vectors v_i
__device__ float4 g_OP4[MM * 256];             // pre-reduced omega_parent mean
__device__ float  g_partZ[MM * NS];
__device__ float  g_partCnt[MM * NS];
__device__ float  g_partS1[MM * NS * KK];
__device__ float  g_partS2[MM * NS * KK * KK];
__device__ float  g_psiPart[MM * 4];

// ---------------------------------------------------------------------------
// Kernel 1: warp-per-system fused reduce+solve (unchanged from R6).
// ---------------------------------------------------------------------------
__global__ void __launch_bounds__(256)
solve_kernel(const float* __restrict__ omega_child,
             const float* __restrict__ mu_s)
{
    __shared__ float A[8][32 * 36];
    const int w = threadIdx.x >> 5, lane = threadIdx.x & 31;
    const int i = blockIdx.x * 8 + w;
    float* Am = A[w];

    const float4* oc4 = (const float4*)(omega_child + (size_t)i * GG * KK * KK);

    // ---- Phase 1: G-reduction. lane handles q = lane + 32j, j=0..7.
    float4 acc[8];
    #pragma unroll
    for (int j = 0; j < 8; j++) acc[j] = oc4[lane + 32 * j];
    #pragma unroll
    for (int g = 1; g < GG; g++) {
        #pragma unroll
        for (int j = 0; j < 8; j++) {
            const float4 v = oc4[g * 256 + lane + 32 * j];
            acc[j].x += v.x; acc[j].y += v.y;
            acc[j].z += v.z; acc[j].w += v.w;
        }
    }
    #pragma unroll
    for (int j = 0; j < 8; j++) {
        const int q = lane + 32 * j;
        *(float4*)(Am + (q >> 3) * 36 + (q & 7) * 4) = acc[j];
    }
    {
        const float* mu = mu_s + (size_t)i * GG * KK;
        float b = 0.f;
        #pragma unroll
        for (int g = 0; g < GG; g++) b += mu[g * KK + lane];
        Am[lane * 36 + 32] = b;
    }
    __syncwarp();

    // ---- Phase 2: forward elimination (warp-private; __syncwarp per k)
    for (int k = 0; k < KK - 1; k++) {
        const float pinv = 1.0f / Am[k * 36 + k];
        const float akc  = Am[k * 36 + lane];
        const float akb  = Am[k * 36 + 32];
        for (int r = k + 1; r < KK; r++) {
            const float m = Am[r * 36 + k] * pinv;
            if (lane > k)  Am[r * 36 + lane] -= m * akc;
            if (lane == k) Am[r * 36 + 32]   -= m * akb;
        }
        __syncwarp();
    }

    // ---- Phase 3: back-substitution (x written into col 32 in place)
    for (int k = KK - 1; k >= 1; k--) {
        const float xk = Am[k * 36 + 32] / Am[k * 36 + k];
        if (lane == k)     Am[k * 36 + 32] = xk;
        else if (lane < k) Am[lane * 36 + 32] -= Am[lane * 36 + k] * xk;
        __syncwarp();
    }
    float xr = Am[lane * 36 + 32];
    if (lane == 0) xr /= Am[0];
    g_V[(size_t)i * KK + lane] = xr;
}

// ---------------------------------------------------------------------------
// Kernel 1b: streaming mean of omega_parent over G -> g_OP4 (512 KB).
// ---------------------------------------------------------------------------
__global__ void reduce_op_kernel(const float4* __restrict__ op4)
{
    const int gid = blockIdx.x * blockDim.x + threadIdx.x;  // 0..32767
    const int a = gid >> 8;
    const int q = gid & 255;
    const float4* p = op4 + (size_t)a * (GG * 256) + q;
    float4 s0 = p[0];
    float4 s1 = p[256];
    #pragma unroll
    for (int g = 2; g < GG; g += 2) {
        const float4 va = p[g * 256];
        const float4 vb = p[(g + 1) * 256];
        s0.x += va.x; s0.y += va.y; s0.z += va.z; s0.w += va.w;
        s1.x += vb.x; s1.y += vb.y; s1.z += vb.z; s1.w += vb.w;
    }
    const float inv = 1.0f / 16.0f;
    s0.x = (s0.x + s1.x) * inv; s0.y = (s0.y + s1.y) * inv;
    s0.z = (s0.z + s1.z) * inv; s0.w = (s0.w + s1.w) * inv;
    g_OP4[gid] = s0;
}

// ---------------------------------------------------------------------------
// Kernel 2: 8x8 register tile, ii-split 8 (as R6) — but launch_bounds(128,3)
// (reg cap 170, was 128) to eliminate spills, and named scalars instead of
// the rv[] local array. Crossbar floor for this shape: ~16us.
// ---------------------------------------------------------------------------
__global__ void __launch_bounds__(128, 3)
accum_kernel(const float* __restrict__ W)
{
    const int a = blockIdx.x;
    const int s = blockIdx.y;
    const int t = threadIdx.x;     // 0..127
    const int i0base = s * CHUNK;

    __shared__ float sw[CHUNK];          // sqrt of masked mean weights (2 KB)
    __shared__ float sx[32 * 36];        // sqrt(w)*v tile, row stride 36
    __shared__ float zred[4], cred[4];

    // ---- Phase 0: preload + reduce all W for this chunk (4 i's per thread)
    float accZ = 0.f, accCnt = 0.f;
    #pragma unroll
    for (int r = 0; r < 4; r++) {
        const int il = t + r * 128;
        const float4* wp =
            (const float4*)(W + ((size_t)(i0base + il) * MM + a) * GG);
        const float4 w0 = wp[0], w1 = wp[1], w2 = wp[2], w3 = wp[3];
        const float sum = (w0.x + w0.y + w0.z + w0.w)
                        + (w1.x + w1.y + w1.z + w1.w)
                        + (w2.x + w2.y + w2.z + w2.w)
                        + (w3.x + w3.y + w3.z + w3.w);
        const float wm = sum * 0.0625f;
        const int ok = (wm >= 1e-6f);
        const float wmm = ok ? wm : 0.0f;
        sw[il] = sqrtf(wmm);
        accZ += wmm;
        accCnt += ok ? 1.0f : 0.0f;
    }
    #pragma unroll
    for (int off = 16; off; off >>= 1) {
        accZ   += __shfl_xor_sync(0xffffffffu, accZ, off);
        accCnt += __shfl_xor_sync(0xffffffffu, accCnt, off);
    }
    if ((t & 31) == 0) { zred[t >> 5] = accZ; cred[t >> 5] = accCnt; }
    __syncthreads();
    if (t == 0) {
        g_partZ[a * NS + s]   = zred[0] + zred[1] + zred[2] + zred[3];
        g_partCnt[a * NS + s] = cred[0] + cred[1] + cred[2] + cred[3];
    }

    const int ig = t >> 4;      // ii-group 0..7
    const int tl = t & 15;
    const int rt = tl >> 2;     // row-oct
    const int ct = tl & 3;      // col-oct
    const int ii_s = t >> 2;    // staging row 0..31
    const int cc_s = t & 3;     // staging quad 0..3

    unsigned long long acc[8][4];
    #pragma unroll
    for (int rr = 0; rr < 8; rr++)
        #pragma unroll
        for (int p = 0; p < 4; p++) acc[rr][p] = 0ull;

    float4 s1a = make_float4(0.f, 0.f, 0.f, 0.f);
    float4 s1b = make_float4(0.f, 0.f, 0.f, 0.f);

    const unsigned sxb = (unsigned)__cvta_generic_to_shared(sx);
    const unsigned rbase = sxb + ig * 4 * 144 + rt * 32;   // row-oct addr
    const unsigned cbase = sxb + ig * 4 * 144 + ct * 32;   // col-oct addr

    // prefetch tile 0
    float4 n0, n1; float wn;
    {
        const float4* vp = (const float4*)g_V + (size_t)(i0base + ii_s) * 8;
        n0 = vp[cc_s]; n1 = vp[cc_s + 4]; wn = sw[ii_s];
    }

    for (int tile = 0; tile < CHUNK / 32; tile++) {
        // ---- stage x = sqrt(w) * v ; accumulate S1 contribution w*v
        {
            float4 x0, x1;
            x0.x = wn * n0.x; x0.y = wn * n0.y; x0.z = wn * n0.z; x0.w = wn * n0.w;
            x1.x = wn * n1.x; x1.y = wn * n1.y; x1.z = wn * n1.z; x1.w = wn * n1.w;
            s1a.x += wn * x0.x; s1a.y += wn * x0.y;
            s1a.z += wn * x0.z; s1a.w += wn * x0.w;
            s1b.x += wn * x1.x; s1b.y += wn * x1.y;
            s1b.z += wn * x1.z; s1b.w += wn * x1.w;
            *(float4*)(sx + ii_s * 36 + cc_s * 4)      = x0;
            *(float4*)(sx + ii_s * 36 + 16 + cc_s * 4) = x1;
        }
        __syncthreads();

        // prefetch next tile (L2 latency hides under the FMA loop)
        if (tile < CHUNK / 32 - 1) {
            const int iloc = (tile + 1) * 32 + ii_s;
            const float4* vp = (const float4*)g_V + (size_t)(i0base + iloc) * 8;
            n0 = vp[cc_s]; n1 = vp[cc_s + 4]; wn = sw[iloc];
        }

        // ---- 8x8 outer-product accumulation over this thread's 4 ii's
        #pragma unroll
        for (int k = 0; k < 4; k++) {
            const unsigned ro = rbase + k * 144;
            const unsigned co = cbase + k * 144;
            float r0, r1, r2, r3, r4_, r5, r6, r7;
            asm volatile("ld.shared.v4.f32 {%0,%1,%2,%3}, [%4];"
                         : "=f"(r0), "=f"(r1), "=f"(r2), "=f"(r3) : "r"(ro));
            asm volatile("ld.shared.v4.f32 {%0,%1,%2,%3}, [%4];"
                         : "=f"(r4_), "=f"(r5), "=f"(r6), "=f"(r7)
                         : "r"(ro + 16));
            unsigned long long c01, c23, c45, c67;
            asm volatile("ld.shared.v2.b64 {%0,%1}, [%2];"
                         : "=l"(c01), "=l"(c23) : "r"(co));
            asm volatile("ld.shared.v2.b64 {%0,%1}, [%2];"
                         : "=l"(c45), "=l"(c67) : "r"(co + 16));
            unsigned long long d;
            #define ROW_FMA(RR, RV)                                          \
                asm("mov.b64 %0, {%1,%1};" : "=l"(d) : "f"(RV));             \
                asm("fma.rn.f32x2 %0, %1, %2, %0;" : "+l"(acc[RR][0])        \
                    : "l"(d), "l"(c01));                                     \
                asm("fma.rn.f32x2 %0, %1, %2, %0;" : "+l"(acc[RR][1])        \
                    : "l"(d), "l"(c23));                                     \
                asm("fma.rn.f32x2 %0, %1, %2, %0;" : "+l"(acc[RR][2])        \
                    : "l"(d), "l"(c45));                                     \
                asm("fma.rn.f32x2 %0, %1, %2, %0;" : "+l"(acc[RR][3])        \
                    : "l"(d), "l"(c67));
            ROW_FMA(0, r0) ROW_FMA(1, r1) ROW_FMA(2, r2) ROW_FMA(3, r3)
            ROW_FMA(4, r4_) ROW_FMA(5, r5) ROW_FMA(6, r6) ROW_FMA(7, r7)
            #undef ROW_FMA
        }
        __syncthreads();
    }

    // ---- S1: dump per-thread partials into sx (free now), reduce over ii
    *(float4*)(sx + ii_s * 36 + cc_s * 4)      = s1a;
    *(float4*)(sx + ii_s * 36 + 16 + cc_s * 4) = s1b;
    __syncthreads();
    if (t < 32) {
        float ssum = 0.f;
        #pragma unroll
        for (int ii = 0; ii < 32; ii++) ssum += sx[ii * 36 + t];
        g_partS1[((size_t)a * NS + s) * KK + t] = ssum;
    }

    // ---- S2: reduce 8 ig-partials per output through smem, 8 rounds.
    float* p2base = g_partS2 + ((size_t)a * NS + s) * (KK * KK);
    #pragma unroll
    for (int rg = 0; rg < 8; rg++) {
        __syncthreads();
        float p0, p1, p2, p3, p4, p5, p6, p7;
        asm("mov.b64 {%0,%1}, %2;" : "=f"(p0), "=f"(p1) : "l"(acc[rg][0]));
        asm("mov.b64 {%0,%1}, %2;" : "=f"(p2), "=f"(p3) : "l"(acc[rg][1]));
        asm("mov.b64 {%0,%1}, %2;" : "=f"(p4), "=f"(p5) : "l"(acc[rg][2]));
        asm("mov.b64 {%0,%1}, %2;" : "=f"(p6), "=f"(p7) : "l"(acc[rg][3]));
        float* dst = sx + ig * 132 + tl * 8;
        *(float4*)dst       = make_float4(p0, p1, p2, p3);
        *(float4*)(dst + 4) = make_float4(p4, p5, p6, p7);
        __syncthreads();
        float ssum = 0.f;
        #pragma unroll
        for (int g = 0; g < 8; g++) ssum += sx[g * 132 + t];
        const int R = (t >> 5) * 8 + rg;
        const int C = ((t >> 3) & 3) * 8 + (t & 7);
        p2base[R * KK + C] = ssum;
    }
}

// ---------------------------------------------------------------------------
// Kernel 3a: psi partials. grid (128 clusters x 4 slices), 256 threads.
// ---------------------------------------------------------------------------
__global__ void finalize_part_kernel(void)
{
    const int a = blockIdx.x;
    const int y = blockIdx.y;
    const int t = threadIdx.x;    // 0..255
    __shared__ float op[32 * 33];
    __shared__ float vbar[32];
    __shared__ float zs;
    __shared__ float red[8];

    {
        const float4 s = g_OP4[a * 256 + t];
        const int e = t * 4;
        const int r = e >> 5, c = e & 31;
        op[r * 33 + c + 0] = s.x;
        op[r * 33 + c + 1] = s.y;
        op[r * 33 + c + 2] = s.z;
        op[r * 33 + c + 3] = s.w;
    }
    if (t == 0) {
        float Z = 0.f;
        #pragma unroll
        for (int ss = 0; ss < NS; ss++) Z += g_partZ[a * NS + ss];
        zs = (Z > 0.f) ? Z : 1.0f;
    }
    if (t < KK) {
        float s1 = 0.f;
        #pragma unroll
        for (int ss = 0; ss < NS; ss++)
            s1 += g_partS1[(a * NS + ss) * KK + t];
        vbar[t] = s1;
    }
    __syncthreads();
    const float Zs = zs;
    if (t < KK) vbar[t] = vbar[t] / Zs;
    __syncthreads();

    const int e = y * 256 + t;
    const int l = e >> 5, m = e & 31;
    float s2 = 0.f;
    #pragma unroll
    for (int ss = 0; ss < NS; ss++)
        s2 += g_partS2[((size_t)a * NS + ss) * (KK * KK) + e];
    const float C = s2 / Zs - vbar[l] * vbar[m];
    float S = 0.f;
    #pragma unroll
    for (int k = 0; k < KK; k++)
        S += op[k * 33 + l] * op[k * 33 + m];
    float psi = S * C;

    #pragma unroll
    for (int off = 16; off; off >>= 1)
        psi += __shfl_xor_sync(0xffffffffu, psi, off);
    if ((t & 31) == 0) red[t >> 5] = psi;
    __syncthreads();
    if (t == 0) {
        float tot = 0.f;
        #pragma unroll
        for (int ww = 0; ww < 8; ww++) tot += red[ww];
        g_psiPart[a * 4 + y] = tot;
    }
}

// ---------------------------------------------------------------------------
// Kernel 3b: combine. One block of 128 threads; thread a -> out[a].
// ---------------------------------------------------------------------------
__global__ void finalize_combine_kernel(float* __restrict__ out)
{
    const int a = threadIdx.x;
    float cnt = 0.f;
    #pragma unroll
    for (int ss = 0; ss < NS; ss++) cnt += g_partCnt[a * NS + ss];
    const float p = g_psiPart[a * 4 + 0] + g_psiPart[a * 4 + 1]
                  + g_psiPart[a * 4 + 2] + g_psiPart[a * 4 + 3];
    out[a] = (cnt >= 2.0f) ? p : 0.0f;
}

// ---------------------------------------------------------------------------
extern "C" void kernel_launch(void* const* d_in, const int* in_sizes, int n_in,
                              void* d_out, int out_size)
{
    const float* W  = (const float*)d_in[0];   // (N, M, G)
    const float* mu = (const float*)d_in[1];   // (N, G, K)
    const float* oc = (const float*)d_in[2];   // (N, G, K, K)
    const float* op = (const float*)d_in[3];   // (M, G, K, K)
    float* out = (float*)d_out;                // (M,)

    solve_kernel<<<NN / 8, 256>>>(oc, mu);
    reduce_op_kernel<<<MM, 256>>>((const float4*)op);
    accum_kernel<<<dim3(MM, NS), 128>>>(W);
    finalize_part_kernel<<<dim3(MM, 4), 256>>>();
    finalize_combine_kernel<<<1, MM>>>(out);
}